// round 16
// baseline (speedup 1.0000x reference)
#include <cuda_runtime.h>
#include <cuda_fp16.h>
#include <cuda_bf16.h>
#include <cstdint>

#define OUT_F 11008
#define IN_F  4096
#define NGROW 32            // groups per output row (4096/128)
#define LUT_N (352256 * 16)
#define TPB   512
#define WPB   16            // warps per block

// Permuted transposed x: slot = (g*4 + j)*32 + lane holds column c = g*128 + 4*lane + j
__device__ float4 g_xa[IN_F];   // batches 0-3
__device__ float4 g_xb[IN_F];   // batches 4-7

__global__ void transpose_x_kernel(const float* __restrict__ x) {
    int c = blockIdx.x * blockDim.x + threadIdx.x;
    if (c < IN_F) {
        int g = c >> 7, w = c & 127, l = w >> 2, j = w & 3;
        int slot = (g * 4 + j) * 32 + l;
        float4 a, b;
        a.x = x[0 * IN_F + c]; a.y = x[1 * IN_F + c];
        a.z = x[2 * IN_F + c]; a.w = x[3 * IN_F + c];
        b.x = x[4 * IN_F + c]; b.y = x[5 * IN_F + c];
        b.z = x[6 * IN_F + c]; b.w = x[7 * IN_F + c];
        g_xa[slot] = a; g_xb[slot] = b;
    }
}

__device__ __forceinline__ bool plaus(float v) {
    float a = fabsf(v);
    return isfinite(v) && a > 1e-4f && a < 0.25f;
}

__device__ __forceinline__ float cvtE(__half v)        { return __half2float(v); }
__device__ __forceinline__ float cvtE(__nv_bfloat16 v) { return __bfloat162float(v); }
__device__ __forceinline__ float cvtE(float v)         { return v; }

__device__ __forceinline__ unsigned long long dup2(float w) {
    unsigned long long r;
    asm("mov.b64 %0, {%1, %1};" : "=l"(r) : "f"(w));
    return r;
}
__device__ __forceinline__ void ffma2(unsigned long long& d,
                                      unsigned long long a,
                                      unsigned long long b) {
    asm("fma.rn.f32x2 %0, %1, %2, %0;" : "+l"(d) : "l"(a), "l"(b));
}

// ---------------- U=2, depth-4 register idx pipeline ----------------
// buf[u][Slot] indexed only by compile-time Slot -> stays in registers.
// ~2KB contiguous idx bytes in flight per row stream -> 4x fewer DRAM
// page activates per byte vs the depth-1 champion.
template <int Slot, typename E>
__device__ __forceinline__ void step2(
    int g,
    int4 (&buf)[2][4],
    const int4* __restrict__ wbase,
    const E* __restrict__ lbase,
    const ulonglong2* __restrict__ xa,
    const ulonglong2* __restrict__ xb,
    unsigned long long (&acc)[2][4],
    int lane)
{
    int4 cur0 = buf[0][Slot];
    int4 cur1 = buf[1][Slot];

    // refill this slot with group g+4 (consumed 3 bodies from now)
    if (g + 4 < NGROW) {
        buf[0][Slot] = __ldcg(wbase + (g + 4) * 32);
        buf[1][Slot] = __ldcg(wbase + (IN_F / 4) + (g + 4) * 32);
    }

#pragma unroll
    for (int j = 0; j < 4; j++) {
        int xoff = (g * 4 + j) * 32 + lane;
        ulonglong2 va = __ldg(&xa[xoff]);   // L1-resident, coalesced
        ulonglong2 vb = __ldg(&xb[xoff]);

        int id0 = reinterpret_cast<const int*>(&cur0)[j];
        int id1 = reinterpret_cast<const int*>(&cur1)[j];
        float w0 = cvtE(__ldg(lbase + g * 16 + id0));
        float w1 = cvtE(__ldg(lbase + (size_t)(NGROW * 16) + g * 16 + id1));
        unsigned long long w20 = dup2(w0);
        unsigned long long w21 = dup2(w1);
        ffma2(acc[0][0], w20, va.x);
        ffma2(acc[0][1], w20, va.y);
        ffma2(acc[0][2], w20, vb.x);
        ffma2(acc[0][3], w20, vb.y);
        ffma2(acc[1][0], w21, va.x);
        ffma2(acc[1][1], w21, va.y);
        ffma2(acc[1][2], w21, vb.x);
        ffma2(acc[1][3], w21, vb.y);
    }
}

template <typename E>
__device__ __forceinline__ void row_pass2(
    const int* __restrict__ widx,
    const E* __restrict__ lut,
    const float* __restrict__ bias,
    float* __restrict__ out,
    int rs, int lane)
{
    const ulonglong2* __restrict__ xa = reinterpret_cast<const ulonglong2*>(g_xa);
    const ulonglong2* __restrict__ xb = reinterpret_cast<const ulonglong2*>(g_xb);

    const int4* wbase = reinterpret_cast<const int4*>(widx) + (size_t)rs * (IN_F / 4) + lane;
    const E*    lbase = lut + (size_t)rs * (NGROW * 16);

    unsigned long long acc[2][4];
#pragma unroll
    for (int u = 0; u < 2; u++)
#pragma unroll
        for (int j = 0; j < 4; j++) acc[u][j] = 0ull;

    int4 buf[2][4];
#pragma unroll
    for (int s = 0; s < 4; s++) {
        buf[0][s] = __ldcg(wbase + s * 32);
        buf[1][s] = __ldcg(wbase + (IN_F / 4) + s * 32);
    }

#pragma unroll 1
    for (int g = 0; g < NGROW; g += 4) {
        step2<0, E>(g,     buf, wbase, lbase, xa, xb, acc, lane);
        step2<1, E>(g + 1, buf, wbase, lbase, xa, xb, acc, lane);
        step2<2, E>(g + 2, buf, wbase, lbase, xa, xb, acc, lane);
        step2<3, E>(g + 3, buf, wbase, lbase, xa, xb, acc, lane);
    }

    float accf[2][8];
#pragma unroll
    for (int u = 0; u < 2; u++)
#pragma unroll
        for (int j = 0; j < 4; j++) {
            unsigned int lo, hi;
            asm("mov.b64 {%0, %1}, %2;" : "=r"(lo), "=r"(hi) : "l"(acc[u][j]));
            accf[u][2 * j]     = __uint_as_float(lo);
            accf[u][2 * j + 1] = __uint_as_float(hi);
        }

#pragma unroll
    for (int off = 16; off > 0; off >>= 1)
#pragma unroll
        for (int u = 0; u < 2; u++)
#pragma unroll
            for (int b = 0; b < 8; b++)
                accf[u][b] += __shfl_xor_sync(0xffffffffu, accf[u][b], off);

    if (lane == 0) {
#pragma unroll
        for (int u = 0; u < 2; u++) {
            float bv = bias[rs + u];
#pragma unroll
            for (int b = 0; b < 8; b++)
                out[(size_t)b * OUT_F + rs + u] = accf[u][b] + bv;
        }
    }
}

// single-row tail (depth-1)
template <typename E>
__device__ __forceinline__ void row_pass1(
    const int* __restrict__ widx,
    const E* __restrict__ lut,
    const float* __restrict__ bias,
    float* __restrict__ out,
    int rs, int lane)
{
    const ulonglong2* __restrict__ xa = reinterpret_cast<const ulonglong2*>(g_xa);
    const ulonglong2* __restrict__ xb = reinterpret_cast<const ulonglong2*>(g_xb);

    const int4* wbase = reinterpret_cast<const int4*>(widx) + (size_t)rs * (IN_F / 4) + lane;
    const E*    lbase = lut + (size_t)rs * (NGROW * 16);

    unsigned long long acc[4];
#pragma unroll
    for (int j = 0; j < 4; j++) acc[j] = 0ull;

    int4 nxt = __ldcg(wbase);

#pragma unroll 1
    for (int g = 0; g < NGROW; g++) {
        int4 cur = nxt;
        if (g + 1 < NGROW) nxt = __ldcg(wbase + (g + 1) * 32);

#pragma unroll
        for (int j = 0; j < 4; j++) {
            int xoff = (g * 4 + j) * 32 + lane;
            ulonglong2 va = __ldg(&xa[xoff]);
            ulonglong2 vb = __ldg(&xb[xoff]);
            int id = reinterpret_cast<const int*>(&cur)[j];
            float w = cvtE(__ldg(lbase + g * 16 + id));
            unsigned long long w2 = dup2(w);
            ffma2(acc[0], w2, va.x);
            ffma2(acc[1], w2, va.y);
            ffma2(acc[2], w2, vb.x);
            ffma2(acc[3], w2, vb.y);
        }
    }

    float accf[8];
#pragma unroll
    for (int j = 0; j < 4; j++) {
        unsigned int lo, hi;
        asm("mov.b64 {%0, %1}, %2;" : "=r"(lo), "=r"(hi) : "l"(acc[j]));
        accf[2 * j]     = __uint_as_float(lo);
        accf[2 * j + 1] = __uint_as_float(hi);
    }
#pragma unroll
    for (int off = 16; off > 0; off >>= 1)
#pragma unroll
        for (int b = 0; b < 8; b++)
            accf[b] += __shfl_xor_sync(0xffffffffu, accf[b], off);

    if (lane == 0) {
        float bv = bias[rs];
#pragma unroll
        for (int b = 0; b < 8; b++)
            out[(size_t)b * OUT_F + rs] = accf[b] + bv;
    }
}

template <typename E>
__device__ __forceinline__ void dispatch_rows(
    const int* __restrict__ widx, const E* __restrict__ lut,
    const float* __restrict__ bias, float* __restrict__ out,
    int rs, int nr, int lane)
{
    int r = rs;
    for (; r + 2 <= rs + nr; r += 2) row_pass2<E>(widx, lut, bias, out, r, lane);
    if (r < rs + nr)                 row_pass1<E>(widx, lut, bias, out, r, lane);
}

__global__ void __launch_bounds__(TPB, 1) pallet_kernel(
    const int* __restrict__ widx,
    const void* __restrict__ lut,
    const float* __restrict__ bias,
    float* __restrict__ out,
    int nwarps)
{
    __shared__ int s_mode;
    int tid = threadIdx.x, warp = tid >> 5, lane = tid & 31;

    // inline dtype probe (warp 0): how was the fp16 LUT materialized?
    if (warp == 0) {
        const unsigned short* s = (const unsigned short*)lut;
        const float* f = (const float*)lut;
        int ch = 0, cb = 0, cf = 0;
        for (int t = lane; t < 64; t += 32) {
            unsigned short v = s[t];
            if (plaus(__half2float(__ushort_as_half(v)))) ch++;
            if (plaus(__uint_as_float(((unsigned)v) << 16))) cb++;   // bf16 -> f32
            if (plaus(f[t])) cf++;
        }
#pragma unroll
        for (int o = 16; o > 0; o >>= 1) {
            ch += __shfl_xor_sync(0xffffffffu, ch, o);
            cb += __shfl_xor_sync(0xffffffffu, cb, o);
            cf += __shfl_xor_sync(0xffffffffu, cf, o);
        }
        if (lane == 0) {
            int m = 0, best = ch;
            if (cb > best) { best = cb; m = 1; }
            if (cf > best) { best = cf; m = 2; }
            s_mode = m;
        }
    }
    __syncthreads();
    int mode = s_mode;

    int w = blockIdx.x * WPB + warp;
    long long s = ((long long)w * OUT_F) / nwarps;
    long long e = ((long long)(w + 1) * OUT_F) / nwarps;
    int rs = (int)s;
    int nr = (int)(e - s);

    if (mode == 0)
        dispatch_rows<__half>(widx, (const __half*)lut, bias, out, rs, nr, lane);
    else if (mode == 1)
        dispatch_rows<__nv_bfloat16>(widx, (const __nv_bfloat16*)lut, bias, out, rs, nr, lane);
    else
        dispatch_rows<float>(widx, (const float*)lut, bias, out, rs, nr, lane);
}

extern "C" void kernel_launch(void* const* d_in, const int* in_sizes, int n_in,
                              void* d_out, int out_size) {
    // Bind inputs by element count (all four distinct):
    //   x: 32768, weight_indices: 45088768, lut: 5636096, bias: 11008
    const float* x    = nullptr;
    const int*   widx = nullptr;
    const void*  lut  = nullptr;
    const float* bias = nullptr;

    for (int i = 0; i < n_in; i++) {
        long long n = in_sizes[i];
        if (n == 8LL * IN_F)                   x    = (const float*)d_in[i];
        else if (n == (long long)OUT_F * IN_F) widx = (const int*)d_in[i];
        else if (n == (long long)LUT_N)        lut  = d_in[i];
        else if (n == OUT_F)                   bias = (const float*)d_in[i];
    }
    if (!x || !widx || !lut || !bias) {
        x    = (const float*)d_in[0];
        widx = (const int*)d_in[1];
        lut  = d_in[2];
        bias = (const float*)d_in[3];
    }

    float* out = (float*)d_out;

    int dev = 0, sms = 148;
    cudaGetDevice(&dev);
    cudaDeviceGetAttribute(&sms, cudaDevAttrMultiProcessorCount, dev);

    transpose_x_kernel<<<(IN_F + 255) / 256, 256>>>(x);
    pallet_kernel<<<sms, TPB>>>(widx, lut, bias, out, sms * WPB);
}

// round 17
// speedup vs baseline: 1.4766x; 1.4766x over previous
#include <cuda_runtime.h>
#include <cuda_fp16.h>
#include <cuda_bf16.h>
#include <cstdint>

#define OUT_F 11008
#define IN_F  4096
#define NGROW 32            // groups per output row (4096/128)
#define LUT_N (352256 * 16)
#define TPB   512
#define WPB   16            // warps per block
#define STAGES 3
#define UMAX  5

#define IDX_WARP_BYTES (STAGES * UMAX * 512)        // 7680
#define SMEM_IDX_BYTES (WPB * IDX_WARP_BYTES)       // 122880
#define LUT_WARP_BYTES (STAGES * UMAX * 64)         // 960
#define SMEM_LUT_BYTES (WPB * LUT_WARP_BYTES)       // 15360
#define SMEM_TOTAL (SMEM_IDX_BYTES + SMEM_LUT_BYTES) // 138240

// Permuted transposed x: slot = (g*4 + j)*32 + lane holds column c = g*128 + 4*lane + j
__device__ float4 g_xa[IN_F];   // batches 0-3
__device__ float4 g_xb[IN_F];   // batches 4-7

__global__ void transpose_x_kernel(const float* __restrict__ x) {
    int c = blockIdx.x * blockDim.x + threadIdx.x;
    if (c < IN_F) {
        int g = c >> 7, w = c & 127, l = w >> 2, j = w & 3;
        int slot = (g * 4 + j) * 32 + l;
        float4 a, b;
        a.x = x[0 * IN_F + c]; a.y = x[1 * IN_F + c];
        a.z = x[2 * IN_F + c]; a.w = x[3 * IN_F + c];
        b.x = x[4 * IN_F + c]; b.y = x[5 * IN_F + c];
        b.z = x[6 * IN_F + c]; b.w = x[7 * IN_F + c];
        g_xa[slot] = a; g_xb[slot] = b;
    }
}

__device__ __forceinline__ bool plaus(float v) {
    float a = fabsf(v);
    return isfinite(v) && a > 1e-4f && a < 0.25f;
}

__device__ __forceinline__ float cvtE(__half v)        { return __half2float(v); }
__device__ __forceinline__ float cvtE(__nv_bfloat16 v) { return __bfloat162float(v); }
__device__ __forceinline__ float cvtE(float v)         { return v; }

__device__ __forceinline__ unsigned long long dup2(float w) {
    unsigned long long r;
    asm("mov.b64 %0, {%1, %1};" : "=l"(r) : "f"(w));
    return r;
}
__device__ __forceinline__ void ffma2(unsigned long long& d,
                                      unsigned long long a,
                                      unsigned long long b) {
    asm("fma.rn.f32x2 %0, %1, %2, %0;" : "+l"(d) : "l"(a), "l"(b));
}

__device__ __forceinline__ void cpa16(uint32_t dst, const void* src) {
    asm volatile("cp.async.cg.shared.global [%0], [%1], 16;" :: "r"(dst), "l"(src));
}
__device__ __forceinline__ void cpa_commit() {
    asm volatile("cp.async.commit_group;");
}
template <int N>
__device__ __forceinline__ void cpa_wait() {
    asm volatile("cp.async.wait_group %0;" :: "n"(N));
}

template <int U, typename E>
__device__ __forceinline__ void row_pass(
    char* smem, uint32_t smem_u32,
    const int* __restrict__ widx,
    const E* __restrict__ lut,
    const float* __restrict__ bias,
    float* __restrict__ out,
    int rs, int lane, int warp)
{
    const ulonglong2* __restrict__ xa = reinterpret_cast<const ulonglong2*>(g_xa);
    const ulonglong2* __restrict__ xb = reinterpret_cast<const ulonglong2*>(g_xb);

    const int4* wbase = reinterpret_cast<const int4*>(widx) + (size_t)rs * (IN_F / 4) + lane;
    const E*    lrow  = lut + (size_t)rs * (NGROW * 16);

    const int widx_off = warp * IDX_WARP_BYTES;
    const int wlut_off = SMEM_IDX_BYTES + warp * LUT_WARP_BYTES;

    unsigned long long acc[U][4];
#pragma unroll
    for (int u = 0; u < U; u++)
#pragma unroll
        for (int j = 0; j < 4; j++) acc[u][j] = 0ull;

    // stage-fill: idx (one int4 per lane per row) + LUT rows (16*sizeof(E) bytes)
    auto fill = [&](int g) {
        int st = g % STAGES;
#pragma unroll
        for (int u = 0; u < U; u++) {
            uint32_t d = smem_u32 + widx_off + (st * UMAX + u) * 512 + lane * 16;
            cpa16(d, wbase + u * (IN_F / 4) + g * 32);
        }
        if (lane < (int)sizeof(E)) {
#pragma unroll
            for (int u = 0; u < U; u++) {
                uint32_t d = smem_u32 + wlut_off + (st * UMAX + u) * 64 + lane * 16;
                cpa16(d, (const char*)(lrow + (size_t)u * (NGROW * 16) + g * 16) + lane * 16);
            }
        }
        cpa_commit();
    };

    fill(0);
    fill(1);

    for (int g = 0; g < NGROW; g++) {
        if (g + STAGES - 1 < NGROW) cpa_wait<STAGES - 2>();
        else                        cpa_wait<0>();
        __syncwarp();

        int st = g % STAGES;
        int4 cur[U];
#pragma unroll
        for (int u = 0; u < U; u++)
            cur[u] = *reinterpret_cast<const int4*>(
                smem + widx_off + (st * UMAX + u) * 512 + lane * 16);

        // kick off the next stage before the FFMA body (targets a different stage)
        {
            int gn = g + STAGES - 1;
            if (gn < NGROW) fill(gn);
        }

#pragma unroll
        for (int j = 0; j < 4; j++) {
            int xoff = (g * 4 + j) * 32 + lane;
            ulonglong2 va = __ldg(&xa[xoff]);   // L1-resident, coalesced
            ulonglong2 vb = __ldg(&xb[xoff]);
#pragma unroll
            for (int u = 0; u < U; u++) {
                int id = reinterpret_cast<const int*>(&cur[u])[j];
                const E* lp = reinterpret_cast<const E*>(
                    smem + wlut_off + (st * UMAX + u) * 64);
                float w = cvtE(lp[id]);          // conflict-free LDS
                unsigned long long w2 = dup2(w);
                ffma2(acc[u][0], w2, va.x);
                ffma2(acc[u][1], w2, va.y);
                ffma2(acc[u][2], w2, vb.x);
                ffma2(acc[u][3], w2, vb.y);
            }
        }
    }

    // unpack and warp-reduce
    float accf[U][8];
#pragma unroll
    for (int u = 0; u < U; u++)
#pragma unroll
        for (int j = 0; j < 4; j++) {
            unsigned int lo, hi;
            asm("mov.b64 {%0, %1}, %2;" : "=r"(lo), "=r"(hi) : "l"(acc[u][j]));
            accf[u][2 * j]     = __uint_as_float(lo);
            accf[u][2 * j + 1] = __uint_as_float(hi);
        }

#pragma unroll
    for (int off = 16; off > 0; off >>= 1)
#pragma unroll
        for (int u = 0; u < U; u++)
#pragma unroll
            for (int b = 0; b < 8; b++)
                accf[u][b] += __shfl_xor_sync(0xffffffffu, accf[u][b], off);

    if (lane == 0) {
#pragma unroll
        for (int u = 0; u < U; u++) {
            float bv = bias[rs + u];
#pragma unroll
            for (int b = 0; b < 8; b++)
                out[(size_t)b * OUT_F + rs + u] = accf[u][b] + bv;
        }
    }
}

template <typename E>
__device__ __forceinline__ void dispatch_rows(
    char* smem, uint32_t smem_u32,
    const int* __restrict__ widx, const E* __restrict__ lut,
    const float* __restrict__ bias, float* __restrict__ out,
    int rs, int nr, int lane, int warp)
{
    switch (nr) {
        case 4: row_pass<4, E>(smem, smem_u32, widx, lut, bias, out, rs, lane, warp); break;
        case 5: row_pass<5, E>(smem, smem_u32, widx, lut, bias, out, rs, lane, warp); break;
        case 3: row_pass<3, E>(smem, smem_u32, widx, lut, bias, out, rs, lane, warp); break;
        case 2: row_pass<2, E>(smem, smem_u32, widx, lut, bias, out, rs, lane, warp); break;
        case 1: row_pass<1, E>(smem, smem_u32, widx, lut, bias, out, rs, lane, warp); break;
        default: {
            int r = rs;
            for (; r + 4 <= rs + nr; r += 4)
                row_pass<4, E>(smem, smem_u32, widx, lut, bias, out, r, lane, warp);
            for (; r < rs + nr; r++)
                row_pass<1, E>(smem, smem_u32, widx, lut, bias, out, r, lane, warp);
            break;
        }
    }
}

__global__ void __launch_bounds__(TPB, 1) pallet_kernel(
    const int* __restrict__ widx,
    const void* __restrict__ lut,
    const float* __restrict__ bias,
    float* __restrict__ out,
    int nwarps)
{
    extern __shared__ char smem[];
    uint32_t smem_u32 = (uint32_t)__cvta_generic_to_shared(smem);
    __shared__ int s_mode;

    int tid = threadIdx.x, warp = tid >> 5, lane = tid & 31;

    // inline dtype probe (warp 0, 64 samples): how was the fp16 LUT materialized?
    if (warp == 0) {
        const unsigned short* s = (const unsigned short*)lut;
        const float* f = (const float*)lut;
        int ch = 0, cb = 0, cf = 0;
        for (int t = lane; t < 64; t += 32) {
            unsigned short v = s[t];
            if (plaus(__half2float(__ushort_as_half(v)))) ch++;
            if (plaus(__uint_as_float(((unsigned)v) << 16))) cb++;   // bf16 -> f32
            if (plaus(f[t])) cf++;
        }
#pragma unroll
        for (int o = 16; o > 0; o >>= 1) {
            ch += __shfl_xor_sync(0xffffffffu, ch, o);
            cb += __shfl_xor_sync(0xffffffffu, cb, o);
            cf += __shfl_xor_sync(0xffffffffu, cf, o);
        }
        if (lane == 0) {
            int m = 0, best = ch;
            if (cb > best) { best = cb; m = 1; }
            if (cf > best) { best = cf; m = 2; }
            s_mode = m;
        }
    }
    __syncthreads();
    int mode = s_mode;

    int w = blockIdx.x * WPB + warp;
    long long s = ((long long)w * OUT_F) / nwarps;
    long long e = ((long long)(w + 1) * OUT_F) / nwarps;
    int rs = (int)s;
    int nr = (int)(e - s);

    if (mode == 0)
        dispatch_rows<__half>(smem, smem_u32, widx, (const __half*)lut, bias, out, rs, nr, lane, warp);
    else if (mode == 1)
        dispatch_rows<__nv_bfloat16>(smem, smem_u32, widx, (const __nv_bfloat16*)lut, bias, out, rs, nr, lane, warp);
    else
        dispatch_rows<float>(smem, smem_u32, widx, (const float*)lut, bias, out, rs, nr, lane, warp);
}

extern "C" void kernel_launch(void* const* d_in, const int* in_sizes, int n_in,
                              void* d_out, int out_size) {
    // Bind inputs by element count (all four distinct):
    //   x: 32768, weight_indices: 45088768, lut: 5636096, bias: 11008
    const float* x    = nullptr;
    const int*   widx = nullptr;
    const void*  lut  = nullptr;
    const float* bias = nullptr;

    for (int i = 0; i < n_in; i++) {
        long long n = in_sizes[i];
        if (n == 8LL * IN_F)                   x    = (const float*)d_in[i];
        else if (n == (long long)OUT_F * IN_F) widx = (const int*)d_in[i];
        else if (n == (long long)LUT_N)        lut  = d_in[i];
        else if (n == OUT_F)                   bias = (const float*)d_in[i];
    }
    if (!x || !widx || !lut || !bias) {
        x    = (const float*)d_in[0];
        widx = (const int*)d_in[1];
        lut  = d_in[2];
        bias = (const float*)d_in[3];
    }

    float* out = (float*)d_out;

    int dev = 0, sms = 148;
    cudaGetDevice(&dev);
    cudaDeviceGetAttribute(&sms, cudaDevAttrMultiProcessorCount, dev);

    cudaFuncSetAttribute(pallet_kernel,
                         cudaFuncAttributeMaxDynamicSharedMemorySize, SMEM_TOTAL);

    transpose_x_kernel<<<(IN_F + 255) / 256, 256>>>(x);
    pallet_kernel<<<sms, TPB, SMEM_TOTAL>>>(widx, lut, bias, out, sms * WPB);
}